// round 16
// baseline (speedup 1.0000x reference)
#include <cuda_runtime.h>
#include <cstdint>

#define NUM_NEURONS 8192
#define INPUT_SIZE  8192
#define BATCH       2048

#define THREADS 512
#define NPT     16                 // neurons per thread (4 groups of 4)
#define GRID    148                // persistent: 1 block per SM
#define PAIRS   (BATCH / 2)        // 1024 row-pairs
#define PAIR_BYTES (2 * INPUT_SIZE * 4)   // 64 KB

// Per-neuron collapsed coefficients: out = A + B*a1 + C*a2 + D*a1*a2
__device__ float4 g_coeff[NUM_NEURONS];

// Per-op affine coefficients (const, a1, a2, a1*a2) for the 16 logic ops.
__constant__ float4 c_op[16] = {
    {0.f,  0.f,  0.f,  0.f}, {0.f,  0.f,  0.f,  1.f},
    {0.f,  1.f,  0.f, -1.f}, {0.f,  1.f,  0.f,  0.f},
    {0.f,  0.f,  1.f, -1.f}, {0.f,  0.f,  1.f,  0.f},
    {0.f,  1.f,  1.f, -2.f}, {0.f,  1.f,  1.f, -1.f},
    {1.f, -1.f, -1.f,  1.f}, {1.f, -1.f, -1.f,  2.f},
    {1.f,  0.f, -1.f,  0.f}, {1.f,  0.f, -1.f,  1.f},
    {1.f, -1.f,  0.f,  0.f}, {1.f, -1.f,  0.f,  1.f},
    {1.f,  0.f,  0.f, -1.f}, {1.f,  0.f,  0.f,  0.f},
};

// ---------------------------------------------------------------------------
// Warp-parallel coefficient precompute: 16 lanes per neuron (one per op).
// ---------------------------------------------------------------------------
__global__ void coeff_kernel(const float* __restrict__ w) {
    const int gt = blockIdx.x * blockDim.x + threadIdx.x;
    const int n = gt >> 4;
    const int j = gt & 15;
    if (n >= NUM_NEURONS) return;

    const float wv = __ldg(&w[(n << 4) + j]);
    float m = wv;
#pragma unroll
    for (int o = 8; o; o >>= 1) m = fmaxf(m, __shfl_xor_sync(0xFFFFFFFFu, m, o, 16));
    const float e = __expf(wv - m);
    float s = e;
#pragma unroll
    for (int o = 8; o; o >>= 1) s += __shfl_xor_sync(0xFFFFFFFFu, s, o, 16);
    const float p = e / s;

    const float4 c = c_op[j];
    float A = p * c.x, B = p * c.y, C = p * c.z, D = p * c.w;
#pragma unroll
    for (int o = 8; o; o >>= 1) {
        A += __shfl_xor_sync(0xFFFFFFFFu, A, o, 16);
        B += __shfl_xor_sync(0xFFFFFFFFu, B, o, 16);
        C += __shfl_xor_sync(0xFFFFFFFFu, C, o, 16);
        D += __shfl_xor_sync(0xFFFFFFFFu, D, o, 16);
    }
    if (j == 0) g_coeff[n] = make_float4(A, B, C, D);
}

// ---------------------------------------------------------------------------
// PTX helpers (mbarrier + 1D TMA bulk copy + named barriers)
// ---------------------------------------------------------------------------
__device__ __forceinline__ uint32_t smem_u32(const void* p) {
    uint32_t a;
    asm("{ .reg .u64 t; cvta.to.shared.u64 t, %1; cvt.u32.u64 %0, t; }"
        : "=r"(a) : "l"(p));
    return a;
}
__device__ __forceinline__ void mbar_init(uint32_t m, uint32_t cnt) {
    asm volatile("mbarrier.init.shared.b64 [%0], %1;" :: "r"(m), "r"(cnt) : "memory");
}
__device__ __forceinline__ void mbar_expect_tx(uint32_t m, uint32_t bytes) {
    asm volatile("mbarrier.arrive.expect_tx.shared.b64 _, [%0], %1;"
                 :: "r"(m), "r"(bytes) : "memory");
}
__device__ __forceinline__ void mbar_wait(uint32_t m, uint32_t phase) {
    asm volatile(
        "{\n\t.reg .pred P;\n\t"
        "WL_%=:\n\t"
        "mbarrier.try_wait.parity.acquire.cta.shared::cta.b64 P, [%0], %1, 0x989680;\n\t"
        "@P bra WD_%=;\n\t"
        "bra WL_%=;\n\t"
        "WD_%=:\n\t}"
        :: "r"(m), "r"(phase) : "memory");
}
__device__ __forceinline__ void tma_bulk_g2s(uint32_t dst_smem, const void* src,
                                             uint32_t bytes, uint32_t mbar) {
    asm volatile(
        "cp.async.bulk.shared::cluster.global.mbarrier::complete_tx::bytes "
        "[%0], [%1], %2, [%3];"
        :: "r"(dst_smem), "l"(src), "r"(bytes), "r"(mbar) : "memory");
}
__device__ __forceinline__ void nbar_arrive(int id) {
    asm volatile("bar.arrive %0, %1;" :: "r"(id), "r"(THREADS) : "memory");
}
__device__ __forceinline__ void nbar_sync(int id) {
    asm volatile("bar.sync %0, %1;" :: "r"(id), "r"(THREADS) : "memory");
}

// ---------------------------------------------------------------------------
// Persistent main kernel. R13 structure (best stable ncu time: 23.0us) with
// ONE change: the per-pair full-block __syncthreads is replaced by a named
// producer barrier. Warps 1-15 bar.arrive (non-blocking) and flow directly
// into pair k+1's mbar wait + gather; ONLY warp 0 bar.syncs (proving all
// reads of buffer b are done) and then issues the TMA for pair k+2.
// Barrier IDs alternate 1/2 with pair parity to prevent phase-slip; skew is
// bounded at one pair because pair k+2's data can't arrive before warp 0
// issues its TMA.
// ---------------------------------------------------------------------------
__global__ __launch_bounds__(THREADS, 1) void logic_kernel(
    const float* __restrict__ x,
    const int*   __restrict__ idx,
    float* __restrict__ out)
{
    extern __shared__ __align__(128) char smem[];
    float* buf0 = reinterpret_cast<float*>(smem);                 // 64 KB
    float* buf1 = reinterpret_cast<float*>(smem + PAIR_BYTES);    // 64 KB
    const uint32_t mbar0 = smem_u32(smem + 2 * PAIR_BYTES);
    const uint32_t mbar1 = mbar0 + 8;

    const int tid = threadIdx.x;
    const int wid = tid >> 5;
    const int bid = blockIdx.x;

    // --- Preload idx (packed u16 pairs) + coefficients into registers ---
    uint32_t pidx[NPT];
    float4   cf[NPT];
    const int4* idx4 = reinterpret_cast<const int4*>(idx);  // 2 neurons per int4
#pragma unroll
    for (int g = 0; g < 4; g++) {
        int nbase = g * 2048 + tid * 4;            // 4 consecutive neurons
        int4 ia = __ldg(&idx4[nbase / 2]);         // neurons nbase, nbase+1
        int4 ib = __ldg(&idx4[nbase / 2 + 1]);     // neurons nbase+2, nbase+3
        pidx[g * 4 + 0] = (uint32_t)ia.x | ((uint32_t)ia.y << 16);
        pidx[g * 4 + 1] = (uint32_t)ia.z | ((uint32_t)ia.w << 16);
        pidx[g * 4 + 2] = (uint32_t)ib.x | ((uint32_t)ib.y << 16);
        pidx[g * 4 + 3] = (uint32_t)ib.z | ((uint32_t)ib.w << 16);
#pragma unroll
        for (int u = 0; u < 4; u++) cf[g * 4 + u] = g_coeff[nbase + u];
    }

    if (tid == 0) { mbar_init(mbar0, 1); mbar_init(mbar1, 1); }
    __syncthreads();

    const int npairs = (PAIRS - bid + GRID - 1) / GRID;   // 6 or 7

    // --- Prologue: issue first two TMA loads ---
    if (tid == 0) {
        if (npairs > 0) {
            mbar_expect_tx(mbar0, PAIR_BYTES);
            tma_bulk_g2s(smem_u32(buf0), x + (size_t)bid * 2 * INPUT_SIZE,
                         PAIR_BYTES, mbar0);
        }
        if (npairs > 1) {
            mbar_expect_tx(mbar1, PAIR_BYTES);
            tma_bulk_g2s(smem_u32(buf1), x + (size_t)(bid + GRID) * 2 * INPUT_SIZE,
                         PAIR_BYTES, mbar1);
        }
    }

    uint32_t phases = 0;   // bit b = current wait parity of buffer b

    for (int k = 0; k < npairs; k++) {
        const int b = k & 1;
        const float* xs0 = b ? buf1 : buf0;
        const float* xs1 = xs0 + INPUT_SIZE;
        const uint32_t mb = b ? mbar1 : mbar0;

        mbar_wait(mb, (phases >> b) & 1u);
        phases ^= (1u << b);

        const int p = bid + k * GRID;
        float4* o0 = reinterpret_cast<float4*>(out + (size_t)(2 * p)     * NUM_NEURONS);
        float4* o1 = reinterpret_cast<float4*>(out + (size_t)(2 * p + 1) * NUM_NEURONS);

#pragma unroll
        for (int g = 0; g < 4; g++) {
            float4 r0, r1;
            float* q0 = reinterpret_cast<float*>(&r0);
            float* q1 = reinterpret_cast<float*>(&r1);
#pragma unroll
            for (int u = 0; u < 4; u++) {
                const uint32_t pk = pidx[g * 4 + u];
                const int i1 = pk & 0xFFFFu;
                const int i2 = pk >> 16;
                const float a10 = xs0[i1], a20 = xs0[i2];
                const float a11 = xs1[i1], a21 = xs1[i2];
                const float4 c = cf[g * 4 + u];
                q0[u] = fmaf(a10, fmaf(a20, c.w, c.y), fmaf(a20, c.z, c.x));
                q1[u] = fmaf(a11, fmaf(a21, c.w, c.y), fmaf(a21, c.z, c.x));
            }
            const int o = g * THREADS + tid;   // coalesced float4 stores
            o0[o] = r0;
            o1[o] = r1;
        }

        // --- Split barrier: warps 1-15 arrive and flow into pair k+1;
        //     warp 0 waits for the full block, then issues TMA k+2 into
        //     the buffer everyone just finished reading. IDs alternate 1/2.
        const int barid = 1 + b;
        if (wid == 0) {
            nbar_sync(barid);                   // all 512 threads done with buf b
            if (tid == 0 && k + 2 < npairs) {
                mbar_expect_tx(mb, PAIR_BYTES);
                tma_bulk_g2s(smem_u32(b ? buf1 : buf0),
                             x + (size_t)(bid + (k + 2) * GRID) * 2 * INPUT_SIZE,
                             PAIR_BYTES, mb);
            }
        } else {
            nbar_arrive(barid);                 // non-blocking
        }
    }
}

extern "C" void kernel_launch(void* const* d_in, const int* in_sizes, int n_in,
                              void* d_out, int out_size) {
    const float* x    = (const float*)d_in[0];   // [2048, 8192] f32
    const float* w    = (const float*)d_in[1];   // [8192, 16]   f32
    const int*   conn = (const int*)d_in[2];     // [8192, 2]    i32
    float* out = (float*)d_out;                  // [2048, 8192] f32

    const int smem = 2 * PAIR_BYTES + 16;        // 128 KB buffers + 2 mbarriers
    cudaFuncSetAttribute(logic_kernel,
                         cudaFuncAttributeMaxDynamicSharedMemorySize, smem);

    coeff_kernel<<<(NUM_NEURONS * 16) / 256, 256>>>(w);
    logic_kernel<<<GRID, THREADS, smem>>>(x, conn, out);
}

// round 17
// speedup vs baseline: 1.0164x; 1.0164x over previous
#include <cuda_runtime.h>
#include <cstdint>

#define NUM_NEURONS 8192
#define INPUT_SIZE  8192
#define BATCH       2048

#define THREADS 512
#define NPT     16                 // neurons per thread (4 groups of 4)
#define GRID    148                // persistent: 1 block per SM, exactly 1 wave
#define PAIRS   (BATCH / 2)        // 1024 row-pairs
#define PAIR_BYTES (2 * INPUT_SIZE * 4)   // 64 KB
#define NPERBLK 56                 // ceil(8192/148) coeff neurons per block

// Per-neuron collapsed coefficients: out = A + B*a1 + C*a2 + D*a1*a2
__device__ float4 g_coeff[NUM_NEURONS];
// Monotonic grid-sync ticket counter (never reset; survives graph replays).
__device__ unsigned long long g_ctr;

// ---------------------------------------------------------------------------
// PTX helpers (mbarrier + 1D TMA bulk copy)
// ---------------------------------------------------------------------------
__device__ __forceinline__ uint32_t smem_u32(const void* p) {
    uint32_t a;
    asm("{ .reg .u64 t; cvta.to.shared.u64 t, %1; cvt.u32.u64 %0, t; }"
        : "=r"(a) : "l"(p));
    return a;
}
__device__ __forceinline__ void mbar_init(uint32_t m, uint32_t cnt) {
    asm volatile("mbarrier.init.shared.b64 [%0], %1;" :: "r"(m), "r"(cnt) : "memory");
}
__device__ __forceinline__ void mbar_expect_tx(uint32_t m, uint32_t bytes) {
    asm volatile("mbarrier.arrive.expect_tx.shared.b64 _, [%0], %1;"
                 :: "r"(m), "r"(bytes) : "memory");
}
__device__ __forceinline__ void mbar_wait(uint32_t m, uint32_t phase) {
    asm volatile(
        "{\n\t.reg .pred P;\n\t"
        "WL_%=:\n\t"
        "mbarrier.try_wait.parity.acquire.cta.shared::cta.b64 P, [%0], %1, 0x989680;\n\t"
        "@P bra WD_%=;\n\t"
        "bra WL_%=;\n\t"
        "WD_%=:\n\t}"
        :: "r"(m), "r"(phase) : "memory");
}
__device__ __forceinline__ void tma_bulk_g2s(uint32_t dst_smem, const void* src,
                                             uint32_t bytes, uint32_t mbar) {
    asm volatile(
        "cp.async.bulk.shared::cluster.global.mbarrier::complete_tx::bytes "
        "[%0], [%1], %2, [%3];"
        :: "r"(dst_smem), "l"(src), "r"(bytes), "r"(mbar) : "memory");
}

// ---------------------------------------------------------------------------
// Fused persistent kernel. grid=148 (1 block/SM, exactly one wave — all
// blocks co-resident, so a global flag sync cannot deadlock).
//   Phase A: issue the first two TMA loads (overlaps everything below).
//   Phase B: this block computes its 56-neuron slice of g_coeff (<1us).
//   Phase C: grid sync via monotonic ticket counter (replay-safe: each
//            replay adds exactly 148; target = (ticket/148+1)*148).
//   Phase D: preload idx + coeffs into registers; R13 gather/compute loop.
// The coeff work and spin hide inside the first TMA's DRAM latency, and the
// second kernel launch disappears from the graph.
// ---------------------------------------------------------------------------
__global__ __launch_bounds__(THREADS, 1) void logic_kernel(
    const float* __restrict__ x,
    const float* __restrict__ w,
    const int*   __restrict__ idx,
    float* __restrict__ out)
{
    extern __shared__ __align__(128) char smem[];
    float* buf0 = reinterpret_cast<float*>(smem);                 // 64 KB
    float* buf1 = reinterpret_cast<float*>(smem + PAIR_BYTES);    // 64 KB
    const uint32_t mbar0 = smem_u32(smem + 2 * PAIR_BYTES);
    const uint32_t mbar1 = mbar0 + 8;

    const int tid = threadIdx.x;
    const int bid = blockIdx.x;
    const int npairs = (PAIRS - bid + GRID - 1) / GRID;   // 6 or 7

    // --- Phase A: mbarriers + first two TMA loads, ASAP ---
    if (tid == 0) {
        mbar_init(mbar0, 1);
        mbar_init(mbar1, 1);
        asm volatile("fence.proxy.async.shared::cta;" ::: "memory");
        mbar_expect_tx(mbar0, PAIR_BYTES);
        tma_bulk_g2s(smem_u32(buf0), x + (size_t)bid * 2 * INPUT_SIZE,
                     PAIR_BYTES, mbar0);
        if (npairs > 1) {
            mbar_expect_tx(mbar1, PAIR_BYTES);
            tma_bulk_g2s(smem_u32(buf1), x + (size_t)(bid + GRID) * 2 * INPUT_SIZE,
                         PAIR_BYTES, mbar1);
        }
    }

    // --- Phase B: compute this block's slice of the collapsed coefficients ---
    {
        const int n = bid * NPERBLK + tid;     // threads 0..55 active
        if (tid < NPERBLK && n < NUM_NEURONS) {
            const float4* wr = reinterpret_cast<const float4*>(w) + n * 4;
            float v[16];
            float4 t;
            t = wr[0]; v[0]=t.x;  v[1]=t.y;  v[2]=t.z;  v[3]=t.w;
            t = wr[1]; v[4]=t.x;  v[5]=t.y;  v[6]=t.z;  v[7]=t.w;
            t = wr[2]; v[8]=t.x;  v[9]=t.y;  v[10]=t.z; v[11]=t.w;
            t = wr[3]; v[12]=t.x; v[13]=t.y; v[14]=t.z; v[15]=t.w;

            float m = v[0];
#pragma unroll
            for (int i = 1; i < 16; i++) m = fmaxf(m, v[i]);
            float s = 0.0f;
#pragma unroll
            for (int i = 0; i < 16; i++) { v[i] = __expf(v[i] - m); s += v[i]; }
            float inv = 1.0f / s;
#pragma unroll
            for (int i = 0; i < 16; i++) v[i] *= inv;

            //  0:0 1:p 2:a1-p 3:a1 4:a2-p 5:a2 6:a1+a2-2p 7:a1+a2-p
            //  8:1-(a1+a2-p) 9:1-(a1+a2-2p) 10:1-a2 11:1-a2+p
            // 12:1-a1 13:1-a1+p 14:1-p 15:1
            float A = v[8]+v[9]+v[10]+v[11]+v[12]+v[13]+v[14]+v[15];
            float B = (v[2]+v[3]+v[6]+v[7]) - (v[8]+v[9]+v[12]+v[13]);
            float C = (v[4]+v[5]+v[6]+v[7]) - (v[8]+v[9]+v[10]+v[11]);
            float D = v[1]-v[2]-v[4]-2.0f*v[6]-v[7]+v[8]+2.0f*v[9]+v[11]+v[13]-v[14];
            g_coeff[n] = make_float4(A, B, C, D);
        }
    }

    // --- Preload idx while coeffs propagate (independent of Phase B/C) ---
    uint32_t pidx[NPT];
    const int4* idx4 = reinterpret_cast<const int4*>(idx);
#pragma unroll
    for (int g = 0; g < 4; g++) {
        int nbase = g * 2048 + tid * 4;
        int4 ia = __ldg(&idx4[nbase / 2]);
        int4 ib = __ldg(&idx4[nbase / 2 + 1]);
        pidx[g * 4 + 0] = (uint32_t)ia.x | ((uint32_t)ia.y << 16);
        pidx[g * 4 + 1] = (uint32_t)ia.z | ((uint32_t)ia.w << 16);
        pidx[g * 4 + 2] = (uint32_t)ib.x | ((uint32_t)ib.y << 16);
        pidx[g * 4 + 3] = (uint32_t)ib.z | ((uint32_t)ib.w << 16);
    }

    // --- Phase C: grid-wide release/acquire sync (one wave -> safe) ---
    __threadfence();           // publish this block's g_coeff slice
    __syncthreads();           // all threads' writes are in
    if (tid == 0) {
        unsigned long long t = atomicAdd(&g_ctr, 1ULL);
        const unsigned long long target = (t / (unsigned long long)GRID + 1ULL) * GRID;
        while (true) {
            unsigned long long v;
            asm volatile("ld.volatile.global.u64 %0, [%1];"
                         : "=l"(v) : "l"(&g_ctr) : "memory");
            if (v >= target) break;
            __nanosleep(64);
        }
    }
    __syncthreads();
    __threadfence();           // acquire: g_coeff writes visible

    // --- Phase D: preload coefficients, then the R13 main loop ---
    float4 cf[NPT];
#pragma unroll
    for (int g = 0; g < 4; g++) {
        int nbase = g * 2048 + tid * 4;
#pragma unroll
        for (int u = 0; u < 4; u++) cf[g * 4 + u] = g_coeff[nbase + u];
    }

    uint32_t phases = 0;   // bit b = current wait parity of buffer b

    for (int k = 0; k < npairs; k++) {
        const int b = k & 1;
        const float* xs0 = b ? buf1 : buf0;
        const float* xs1 = xs0 + INPUT_SIZE;
        const uint32_t mb = b ? mbar1 : mbar0;

        mbar_wait(mb, (phases >> b) & 1u);
        phases ^= (1u << b);

        const int p = bid + k * GRID;
        float4* o0 = reinterpret_cast<float4*>(out + (size_t)(2 * p)     * NUM_NEURONS);
        float4* o1 = reinterpret_cast<float4*>(out + (size_t)(2 * p + 1) * NUM_NEURONS);

#pragma unroll
        for (int g = 0; g < 4; g++) {
            float4 r0, r1;
            float* q0 = reinterpret_cast<float*>(&r0);
            float* q1 = reinterpret_cast<float*>(&r1);
#pragma unroll
            for (int u = 0; u < 4; u++) {
                const uint32_t pk = pidx[g * 4 + u];
                const int i1 = pk & 0xFFFFu;
                const int i2 = pk >> 16;
                const float a10 = xs0[i1], a20 = xs0[i2];
                const float a11 = xs1[i1], a21 = xs1[i2];
                const float4 c = cf[g * 4 + u];
                q0[u] = fmaf(a10, fmaf(a20, c.w, c.y), fmaf(a20, c.z, c.x));
                q1[u] = fmaf(a11, fmaf(a21, c.w, c.y), fmaf(a21, c.z, c.x));
            }
            const int o = g * THREADS + tid;   // coalesced float4 stores
            o0[o] = r0;
            o1[o] = r1;
        }

        __syncthreads();   // everyone done reading buffer b

        if (tid == 0 && k + 2 < npairs) {
            mbar_expect_tx(mb, PAIR_BYTES);
            tma_bulk_g2s(smem_u32(b ? buf1 : buf0),
                         x + (size_t)(bid + (k + 2) * GRID) * 2 * INPUT_SIZE,
                         PAIR_BYTES, mb);
        }
    }
}

extern "C" void kernel_launch(void* const* d_in, const int* in_sizes, int n_in,
                              void* d_out, int out_size) {
    const float* x    = (const float*)d_in[0];   // [2048, 8192] f32
    const float* w    = (const float*)d_in[1];   // [8192, 16]   f32
    const int*   conn = (const int*)d_in[2];     // [8192, 2]    i32
    float* out = (float*)d_out;                  // [2048, 8192] f32

    const int smem = 2 * PAIR_BYTES + 16;        // 128 KB buffers + 2 mbarriers
    cudaFuncSetAttribute(logic_kernel,
                         cudaFuncAttributeMaxDynamicSharedMemorySize, smem);

    logic_kernel<<<GRID, THREADS, smem>>>(x, w, conn, out);
}